// round 9
// baseline (speedup 1.0000x reference)
#include <cuda_runtime.h>

// Problem constants
#define N_CB   8
#define VOCAB  1024
#define VSLICE 128          // vocab entries per block (8-way split)
#define CDIM   16
#define BATCH  8
#define HW     1024         // 32*32
#define DCH    128          // N_CB*CDIM
#define BHW    8192         // BATCH*HW
#define NITEMS 65536        // BHW * N_CB

// Output layout (float32, concatenated flat in reference order)
#define OFF_Q      0
#define OFF_IDX    1048576
#define OFF_COMMIT 1114112
#define OFF_NCB    1114113
#define OFF_NCNT   1245185
#define OFF_NW     1253377

#define DECAY_F 0.99f
#define ALPHA_F 0.01f
#define EPS_F   1e-5f

// self-cleaning device state (zero-initialized at module load; every kernel
// restores it to zero after consuming it, so graph replays are deterministic)
__device__ unsigned long long vq_scratch[NITEMS];   // argmin: ~((key<<32)|idx); 0 == empty/worst
__device__ float cnt_scr[N_CB * VOCAB];             // raw counts
__device__ float sum_scr[N_CB * VOCAB * CDIM];      // raw z sums
__device__ float n_dev[N_CB];                       // per-cb n (overwritten each run)

// ---------- f32x2 packed helpers ----------
static __device__ __forceinline__ unsigned long long pack2(float lo, float hi) {
    unsigned long long r;
    asm("mov.b64 %0, {%1,%2};" : "=l"(r) : "f"(lo), "f"(hi));
    return r;
}
static __device__ __forceinline__ void unpack2(unsigned long long v, float& lo, float& hi) {
    asm("mov.b64 {%0,%1}, %2;" : "=f"(lo), "=f"(hi) : "l"(v));
}
static __device__ __forceinline__ unsigned long long fma2(unsigned long long a,
                                                          unsigned long long b,
                                                          unsigned long long c) {
    unsigned long long d;
    asm("fma.rn.f32x2 %0, %1, %2, %3;" : "=l"(d) : "l"(a), "l"(b), "l"(c));
    return d;
}
// monotone float -> u32 (order-preserving for all finite floats)
static __device__ __forceinline__ unsigned int fkey(float s) {
    unsigned int b = __float_as_uint(s);
    return (b & 0x80000000u) ? ~b : (b | 0x80000000u);
}

// ---------- kernel 1: distance sweep + argmin ----------
// grid: (32, 8, 8) -> x: chunk of 256 positions, y: codebook, z: vocab slice
// block: 128 threads, 2 positions per thread; low regs -> 6 blocks/SM (24 warps)
// smem per vocab v (10 u64, 80B, 16B aligned):
//   [0..7]  dim-pairs (c[2k], c[2k+1])  -- natural row order
//   [8]     (0.5*||c||^2, 0.0)          -- folded into accumulator init
//   [9]     pad
__global__ __launch_bounds__(128, 6) void vq_main(const float* __restrict__ z,
                                                  const float* __restrict__ cbs,
                                                  float* out) {
    __shared__ __align__(16) unsigned long long sm2[VSLICE * 10];   // 10240 B
    float* smf = (float*)sm2;

    const int cb    = blockIdx.y;
    const int vbase = blockIdx.z * VSLICE;
    const int tid   = threadIdx.x;

    // zero commitment accumulator once per replay (epi launches after main completes)
    if (blockIdx.x == 0 && blockIdx.y == 0 && blockIdx.z == 0 && tid == 0)
        out[OFF_COMMIT] = 0.0f;

    // load slice codebook (natural layout), stride 20 floats per vocab row
    {
        const float* src = cbs + ((size_t)cb * VOCAB + vbase) * CDIM;  // 2048 floats
        #pragma unroll
        for (int t = 0; t < 16; t++) {
            int i = tid + t * 128;
            int v = i >> 4, j = i & 15;
            smf[v * 20 + j] = src[i];
        }
    }
    __syncthreads();
    // h = 0.5||c||^2 per vocab (one vocab per thread, tid<128 covers VSLICE=128)
    {
        const int v = tid;
        const float* r = smf + v * 20;
        float s = 0.0f;
        #pragma unroll
        for (int j = 0; j < CDIM; j++) s += r[j] * r[j];
        smf[v * 20 + 16] = 0.5f * s;
        smf[v * 20 + 17] = 0.0f;
    }
    __syncthreads();

    // two positions per thread (same batch image: chunk of 256 within 1024)
    const int p0 = blockIdx.x * 256 + tid;
    const int b  = p0 >> 10;
    const int hw0 = p0 & (HW - 1);
    const int hw1 = (p0 + 128) & (HW - 1);

    const float* zb = z + (size_t)b * DCH * HW + (size_t)cb * CDIM * HW;

    unsigned long long zz0[8], zz1[8];
    #pragma unroll
    for (int k = 0; k < 8; k++) {
        const float* e = zb + (2 * k) * HW;
        const float* o = zb + (2 * k + 1) * HW;
        zz0[k] = pack2(-e[hw0], -o[hw0]);
        zz1[k] = pack2(-e[hw1], -o[hw1]);
    }

    float best0 = 3.0e38f, best1 = 3.0e38f;
    int   bi0 = 0, bi1 = 0;

    #pragma unroll 2
    for (int v = 0; v < VSLICE; v++) {
        const ulonglong2* row = reinterpret_cast<const ulonglong2*>(sm2 + v * 10);
        ulonglong2 r0 = row[0], r1 = row[1], r2 = row[2], r3 = row[3];
        const unsigned long long h2 = sm2[v * 10 + 8];

        unsigned long long a0, a1;
        a0 = fma2(zz0[0], r0.x, h2); a1 = fma2(zz1[0], r0.x, h2);
        a0 = fma2(zz0[1], r0.y, a0); a1 = fma2(zz1[1], r0.y, a1);
        a0 = fma2(zz0[2], r1.x, a0); a1 = fma2(zz1[2], r1.x, a1);
        a0 = fma2(zz0[3], r1.y, a0); a1 = fma2(zz1[3], r1.y, a1);
        a0 = fma2(zz0[4], r2.x, a0); a1 = fma2(zz1[4], r2.x, a1);
        a0 = fma2(zz0[5], r2.y, a0); a1 = fma2(zz1[5], r2.y, a1);
        a0 = fma2(zz0[6], r3.x, a0); a1 = fma2(zz1[6], r3.x, a1);
        a0 = fma2(zz0[7], r3.y, a0); a1 = fma2(zz1[7], r3.y, a1);

        float lo, hi, s;
        bool t;
        unpack2(a0, lo, hi); s = lo + hi;
        t = s < best0; best0 = t ? s : best0; bi0 = t ? v : bi0;
        unpack2(a1, lo, hi); s = lo + hi;
        t = s < best1; best1 = t ? s : best1; bi1 = t ? v : bi1;
    }

    // combine across vocab slices: atomicMax on complemented keys
    // (max of complements == complement of min; empty slot 0 == worst; ties -> smaller idx)
    unsigned long long* sc = vq_scratch + (size_t)cb * BHW;
    atomicMax(&sc[p0],
              ~(((unsigned long long)fkey(best0) << 32) | (unsigned)(vbase + bi0)));
    atomicMax(&sc[p0 + 128],
              ~(((unsigned long long)fkey(best1) << 32) | (unsigned)(vbase + bi1)));
}

// ---------- kernel 2: epilogue (quantize, indices, scatter, commitment, n) ----------
// grid: (64, 8), block 128, one position per thread
__global__ __launch_bounds__(128) void vq_epi(const float* __restrict__ z,
                                              const float* __restrict__ cbs,
                                              const float* __restrict__ ema_count,
                                              float* out) {
    const int cb  = blockIdx.y;
    const int tid = threadIdx.x;
    const int pos = blockIdx.x * 128 + tid;
    const int b   = pos >> 10;
    const int hw  = pos & (HW - 1);

    // read winner, self-clean the slot
    unsigned long long* scp = vq_scratch + (size_t)cb * BHW + pos;
    const unsigned long long comp = *scp;
    *scp = 0ull;
    const int bi = (int)(unsigned)(~comp);

    const float* crow = cbs + ((size_t)cb * VOCAB + bi) * CDIM;
    const float* zb   = z + (size_t)b * DCH * HW + (size_t)cb * CDIM * HW + hw;

    float* qout = out + OFF_Q + (size_t)b * DCH * HW + (size_t)cb * CDIM * HW + hw;
    float* wdst = sum_scr + ((size_t)cb * VOCAB + bi) * CDIM;

    float locc = 0.0f;
    #pragma unroll
    for (int j = 0; j < CDIM; j++) {
        const float zj = zb[(size_t)j * HW];
        const float cj = crow[j];
        qout[(size_t)j * HW] = zj + (cj - zj);       // match zq_st rounding
        const float d = zj - cj;
        locc += d * d;
        atomicAdd(&wdst[j], zj);                     // raw sums (scaled in vq_final)
    }
    out[OFF_IDX + (size_t)b * (N_CB * HW) + (size_t)cb * HW + hw] = (float)bi;
    atomicAdd(&cnt_scr[cb * VOCAB + bi], 1.0f);      // raw counts

    // commitment: shuffle reduce -> 1 atomic per block
    #pragma unroll
    for (int st = 16; st > 0; st >>= 1)
        locc += __shfl_xor_sync(0xFFFFFFFFu, locc, st);
    __shared__ float red[4];
    if ((tid & 31) == 0) red[tid >> 5] = locc;
    __syncthreads();
    if (tid == 0)
        atomicAdd(out + OFF_COMMIT,
                  (red[0] + red[1] + red[2] + red[3]) * (1.0f / (float)(BHW * N_CB * CDIM)));

    // blocks with x==0 also compute n[cb] = 0.99*sum(ema_count[cb]) + 0.01*BHW
    if (blockIdx.x == 0) {
        float s = 0.0f;
        #pragma unroll
        for (int t = 0; t < 8; t++) s += ema_count[cb * VOCAB + tid + t * 128];
        #pragma unroll
        for (int st = 16; st > 0; st >>= 1)
            s += __shfl_xor_sync(0xFFFFFFFFu, s, st);
        __shared__ float nred[4];
        if ((tid & 31) == 0) nred[tid >> 5] = s;
        __syncthreads();
        if (tid == 0)
            n_dev[cb] = DECAY_F * (nred[0] + nred[1] + nred[2] + nred[3])
                      + ALPHA_F * (float)BHW;
    }
}

// ---------- kernel 3: EMA blend + normalized codebook update ----------
// grid 512 x 256, one weight element per thread
__global__ __launch_bounds__(256) void vq_final(const float* __restrict__ ema_count,
                                                const float* __restrict__ ema_weight,
                                                float* out) {
    const int i  = blockIdx.x * 256 + threadIdx.x;    // 0 .. 131071
    const int cb = i >> 14;
    const int v  = (i >> 4) & (VOCAB - 1);
    const int j  = i & 15;

    const float sums = sum_scr[i];
    sum_scr[i] = 0.0f;                                // self-clean
    const float nw = DECAY_F * ema_weight[i] + ALPHA_F * sums;
    out[OFF_NW + i] = nw;

    const float craw = cnt_scr[cb * VOCAB + v];
    __syncwarp();                                     // all 16 readers done before clean
    if (j == 0) cnt_scr[cb * VOCAB + v] = 0.0f;       // self-clean

    const float ncnt = DECAY_F * ema_count[cb * VOCAB + v] + ALPHA_F * craw;
    if (j == 0) out[OFF_NCNT + cb * VOCAB + v] = ncnt;

    const float n = n_dev[cb];
    const float countv = (ncnt + EPS_F) / (n + VOCAB * EPS_F) * n;
    out[OFF_NCB + i] = __fdividef(nw, countv);
}

extern "C" void kernel_launch(void* const* d_in, const int* in_sizes, int n_in,
                              void* d_out, int out_size) {
    const float* z   = (const float*)d_in[0];
    const float* cbs = (const float*)d_in[1];
    const float* ec  = (const float*)d_in[2];
    const float* ew  = (const float*)d_in[3];
    float* out = (float*)d_out;

    dim3 gmain(32, N_CB, 8);
    vq_main<<<gmain, 128>>>(z, cbs, out);
    dim3 gepi(64, N_CB);
    vq_epi<<<gepi, 128>>>(z, cbs, ec, out);
    vq_final<<<512, 256>>>(ec, ew, out);
}

// round 12
// speedup vs baseline: 1.9051x; 1.9051x over previous
#include <cuda_runtime.h>
#include <cuda_fp16.h>
#include <cstdint>

// Problem constants
#define N_CB   8
#define VOCAB  1024
#define CDIM   16
#define HW     1024         // 32*32
#define DCH    128          // N_CB*CDIM
#define BHW    8192

// Output layout (float32, concatenated flat in reference order)
#define OFF_Q      0
#define OFF_IDX    1048576
#define OFF_COMMIT 1114112
#define OFF_NCB    1114113
#define OFF_NCNT   1245185
#define OFF_NW     1253377

#define DECAY_F 0.99f
#define ALPHA_F 0.01f
#define EPS_F   1e-5f

// staged fp16 split codebook + (-0.5||c||^2) table (recomputed every replay)
__device__ __half chi_g[N_CB * VOCAB * CDIM];
__device__ __half clo_g[N_CB * VOCAB * CDIM];
__device__ float  negh_g[N_CB * VOCAB];
// self-cleaning accumulators (zero at load; vq_final re-zeros each replay)
__device__ float cnt_scr[N_CB * VOCAB];
__device__ float sum_scr[N_CB * VOCAB * CDIM];
__device__ float n_dev[N_CB];
__device__ float commit_scr;

static __device__ __forceinline__ uint32_t smem_u32(const void* p) {
    uint32_t a;
    asm("{ .reg .u64 t; cvta.to.shared.u64 t, %1; cvt.u32.u64 %0, t; }" : "=r"(a) : "l"(p));
    return a;
}

// ---------------- smem layout (static, 46.6 KB) ----------------
#define SM_BHI 0                     // 256 rows x 48B (16 halves + 16B pad)
#define SM_BLO 12288
#define SM_AHI 24576                 // 128 rows x 48B
#define SM_ALO 30720
#define SM_ZF  36864                 // 128 x 16 fp32
#define SM_H   45056                 // 256 floats (-0.5||c||^2 chunk)
#define SM_IDX 46080                 // 128 ints
#define SM_TOT 46592

// ---------- kernel 0: stage fp16 hi/lo codebook + negh ----------
__global__ __launch_bounds__(256) void vq_prep(const float* __restrict__ cbs) {
    const int i = blockIdx.x * 256 + threadIdx.x;       // 0..131071
    const float v = cbs[i];
    const __half hi = __float2half_rn(v);
    const __half lo = __float2half_rn(v - __half2float(hi));
    chi_g[i] = hi;
    clo_g[i] = lo;
    if (i < N_CB * VOCAB) {
        const float4* cr = (const float4*)(cbs + (size_t)i * CDIM);
        float4 c0 = cr[0], c1 = cr[1], c2 = cr[2], c3 = cr[3];
        float s = c0.x*c0.x + c0.y*c0.y + c0.z*c0.z + c0.w*c0.w
                + c1.x*c1.x + c1.y*c1.y + c1.z*c1.z + c1.w*c1.w
                + c2.x*c2.x + c2.y*c2.y + c2.z*c2.z + c2.w*c2.w
                + c3.x*c3.x + c3.y*c3.y + c3.z*c3.z + c3.w*c3.w;
        negh_g[i] = -0.5f * s;
    }
}

// ---------- kernel 1: HMMA distance + argmin + fused epilogue ----------
// grid (64, 8): x = 128-position tile, y = codebook. 256 threads (8 warps).
// warp w owns positions tile*128 + w*16 .. +15 (MMA M-rows).
__global__ __launch_bounds__(256) void vq_main(const float* __restrict__ z,
                                               const float* __restrict__ cbs,
                                               const float* __restrict__ ema_count,
                                               float* out) {
    __shared__ __align__(16) char smem[SM_TOT];
    __shared__ float red[8], nred[8];
    const uint32_t sb = smem_u32(smem);
    const int cb = blockIdx.y, tile = blockIdx.x;
    const int tid = threadIdx.x, lane = tid & 31, w = tid >> 5;

    const int b      = tile >> 3;
    const int hwwarp = ((tile & 7) << 7) + w * 16;
    const float* zb  = z + (size_t)b * DCH * HW + (size_t)cb * CDIM * HW;

    // ---- build A tiles (fp16 hi/lo, 48B row stride) + fp32 z copy ----
    {
        const int r  = lane & 15;          // row within warp tile
        const int jh = lane >> 4;          // 0/1 selects dim parity group
        float* zf = (float*)(smem + SM_ZF);
        #pragma unroll
        for (int j2 = 0; j2 < 8; j2++) {
            const int j = j2 * 2 + jh;
            const float v = zb[j * HW + hwwarp + r];
            const __half hi = __float2half_rn(v);
            const __half lo = __float2half_rn(v - __half2float(hi));
            const int row = w * 16 + r;
            *(__half*)(smem + SM_AHI + row * 48 + j * 2) = hi;
            *(__half*)(smem + SM_ALO + row * 48 + j * 2) = lo;
            zf[row * 16 + j] = v;
        }
    }
    __syncwarp();

    // ---- A fragments (persistent): ldmatrix.x4, canonical m16n16 pattern ----
    uint32_t ah0, ah1, ah2, ah3, al0, al1, al2, al3;
    {
        const uint32_t ofs = (uint32_t)(w * 16 * 48 + (lane & 15) * 48 + ((lane >> 4) << 4));
        uint32_t a = sb + SM_AHI + ofs;
        asm volatile("ldmatrix.sync.aligned.m8n8.x4.shared.b16 {%0,%1,%2,%3}, [%4];"
                     : "=r"(ah0), "=r"(ah1), "=r"(ah2), "=r"(ah3) : "r"(a));
        a = sb + SM_ALO + ofs;
        asm volatile("ldmatrix.sync.aligned.m8n8.x4.shared.b16 {%0,%1,%2,%3}, [%4];"
                     : "=r"(al0), "=r"(al1), "=r"(al2), "=r"(al3) : "r"(a));
    }

    float bestA = -3.0e38f, bestB = -3.0e38f;
    int   vA = 0, vB = 0;
    const int colofs = (lane & 3) * 2;     // D/B column (vocab) offset
    const int nrow   = lane >> 2;          // D row group

    for (int c = 0; c < 4; c++) {
        // ---- copy B chunk (256 vocab rows) to 48B-stride smem + h chunk ----
        {
            const size_t rbase = ((size_t)cb * VOCAB + c * 256 + tid) * CDIM;
            const uint4* sh = (const uint4*)(chi_g + rbase);
            uint4 x0 = sh[0], x1 = sh[1];
            *(uint4*)(smem + SM_BHI + tid * 48)      = x0;
            *(uint4*)(smem + SM_BHI + tid * 48 + 16) = x1;
            const uint4* sl = (const uint4*)(clo_g + rbase);
            uint4 y0 = sl[0], y1 = sl[1];
            *(uint4*)(smem + SM_BLO + tid * 48)      = y0;
            *(uint4*)(smem + SM_BLO + tid * 48 + 16) = y1;
            ((float*)(smem + SM_H))[tid] = negh_g[cb * VOCAB + c * 256 + tid];
        }
        __syncthreads();

        #pragma unroll 4
        for (int it = 0; it < 32; it++) {
            const int vl = it * 8;
            const uint32_t baddr = sb + (uint32_t)((vl + (lane & 7)) * 48 + ((lane >> 3) & 1) * 16);
            uint32_t bh0, bh1, bl0, bl1;
            asm volatile("ldmatrix.sync.aligned.m8n8.x2.shared.b16 {%0,%1}, [%2];"
                         : "=r"(bh0), "=r"(bh1) : "r"(baddr + SM_BHI));
            asm volatile("ldmatrix.sync.aligned.m8n8.x2.shared.b16 {%0,%1}, [%2];"
                         : "=r"(bl0), "=r"(bl1) : "r"(baddr + SM_BLO));
            const float2 hh = *(const float2*)(smem + SM_H + (vl + colofs) * 4);

            float d0, d1, d2, d3;
            asm volatile("mma.sync.aligned.m16n8k16.row.col.f32.f16.f16.f32 "
                "{%0,%1,%2,%3}, {%4,%5,%6,%7}, {%8,%9}, {%10,%11,%12,%13};"
                : "=f"(d0), "=f"(d1), "=f"(d2), "=f"(d3)
                : "r"(ah0), "r"(ah1), "r"(ah2), "r"(ah3), "r"(bh0), "r"(bh1),
                  "f"(hh.x), "f"(hh.y), "f"(hh.x), "f"(hh.y));
            asm volatile("mma.sync.aligned.m16n8k16.row.col.f32.f16.f16.f32 "
                "{%0,%1,%2,%3}, {%4,%5,%6,%7}, {%8,%9}, {%0,%1,%2,%3};"
                : "+f"(d0), "+f"(d1), "+f"(d2), "+f"(d3)
                : "r"(al0), "r"(al1), "r"(al2), "r"(al3), "r"(bh0), "r"(bh1));
            asm volatile("mma.sync.aligned.m16n8k16.row.col.f32.f16.f16.f32 "
                "{%0,%1,%2,%3}, {%4,%5,%6,%7}, {%8,%9}, {%0,%1,%2,%3};"
                : "+f"(d0), "+f"(d1), "+f"(d2), "+f"(d3)
                : "r"(ah0), "r"(ah1), "r"(ah2), "r"(ah3), "r"(bl0), "r"(bl1));

            const int v0 = c * 256 + vl + colofs;
            if (d0 > bestA) { bestA = d0; vA = v0; }
            if (d1 > bestA) { bestA = d1; vA = v0 + 1; }
            if (d2 > bestB) { bestB = d2; vB = v0; }
            if (d3 > bestB) { bestB = d3; vB = v0 + 1; }
        }
        __syncthreads();
    }

    // ---- merge argmax within each quad (lanes sharing a D row) ----
    #pragma unroll
    for (int st = 1; st <= 2; st <<= 1) {
        float so = __shfl_xor_sync(0xFFFFFFFFu, bestA, st);
        int   vo = __shfl_xor_sync(0xFFFFFFFFu, vA, st);
        if (so > bestA || (so == bestA && vo < vA)) { bestA = so; vA = vo; }
        so = __shfl_xor_sync(0xFFFFFFFFu, bestB, st);
        vo = __shfl_xor_sync(0xFFFFFFFFu, vB, st);
        if (so > bestB || (so == bestB && vo < vB)) { bestB = so; vB = vo; }
    }
    if ((lane & 3) == 0) {
        int* idxs = (int*)(smem + SM_IDX);
        idxs[w * 16 + nrow]     = vA;
        idxs[w * 16 + nrow + 8] = vB;
    }
    __syncthreads();

    // ---- fused epilogue: 2 threads per position (8 dims each) ----
    const int pl  = tid >> 1;
    const int j0  = (tid & 1) * 8;
    const int bi  = ((int*)(smem + SM_IDX))[pl];
    const int hwp = ((tile & 7) << 7) + pl;
    const float* crow = cbs + ((size_t)cb * VOCAB + bi) * CDIM + j0;
    const float* zf   = (float*)(smem + SM_ZF) + pl * 16 + j0;
    float* qout = out + OFF_Q + (size_t)b * DCH * HW + (size_t)cb * CDIM * HW
                + (size_t)j0 * HW + hwp;
    float* wdst = sum_scr + ((size_t)cb * VOCAB + bi) * CDIM + j0;

    float locc = 0.0f;
    #pragma unroll
    for (int jj = 0; jj < 8; jj++) {
        const float zj = zf[jj];
        const float cj = crow[jj];
        qout[(size_t)jj * HW] = zj + (cj - zj);      // match zq_st rounding
        const float d = zj - cj;
        locc += d * d;
        atomicAdd(&wdst[jj], zj);
    }
    if ((tid & 1) == 0) {
        out[OFF_IDX + (size_t)b * (N_CB * HW) + (size_t)cb * HW + hwp] = (float)bi;
        atomicAdd(&cnt_scr[cb * VOCAB + bi], 1.0f);
    }

    // commitment: shuffle reduce -> 1 atomic per block
    #pragma unroll
    for (int st = 16; st > 0; st >>= 1)
        locc += __shfl_xor_sync(0xFFFFFFFFu, locc, st);
    if (lane == 0) red[w] = locc;
    __syncthreads();
    if (tid == 0) {
        float s = 0.0f;
        #pragma unroll
        for (int k = 0; k < 8; k++) s += red[k];
        atomicAdd(&commit_scr, s * (1.0f / (float)(BHW * N_CB * CDIM)));
    }

    // tile==0 blocks compute n[cb] = 0.99*sum(ema_count[cb]) + 0.01*BHW
    if (tile == 0) {
        float s = ema_count[cb * VOCAB + tid]       + ema_count[cb * VOCAB + tid + 256]
                + ema_count[cb * VOCAB + tid + 512] + ema_count[cb * VOCAB + tid + 768];
        #pragma unroll
        for (int st = 16; st > 0; st >>= 1)
            s += __shfl_xor_sync(0xFFFFFFFFu, s, st);
        if (lane == 0) nred[w] = s;
        __syncthreads();
        if (tid == 0) {
            float t = 0.0f;
            #pragma unroll
            for (int k = 0; k < 8; k++) t += nred[k];
            n_dev[cb] = DECAY_F * t + ALPHA_F * (float)BHW;
        }
    }
}

// ---------- kernel 2: EMA blend + normalized codebook + commit emit ----------
__global__ __launch_bounds__(256) void vq_final(const float* __restrict__ ema_count,
                                                const float* __restrict__ ema_weight,
                                                float* out) {
    const int i  = blockIdx.x * 256 + threadIdx.x;    // 0 .. 131071
    const int cb = i >> 14;
    const int v  = (i >> 4) & (VOCAB - 1);
    const int j  = i & 15;

    if (i == 0) { out[OFF_COMMIT] = commit_scr; commit_scr = 0.0f; }

    const float sums = sum_scr[i];
    sum_scr[i] = 0.0f;                                // self-clean
    const float nw = DECAY_F * ema_weight[i] + ALPHA_F * sums;
    out[OFF_NW + i] = nw;

    const float craw = cnt_scr[cb * VOCAB + v];
    __syncwarp();
    if (j == 0) cnt_scr[cb * VOCAB + v] = 0.0f;       // self-clean

    const float ncnt = DECAY_F * ema_count[cb * VOCAB + v] + ALPHA_F * craw;
    if (j == 0) out[OFF_NCNT + cb * VOCAB + v] = ncnt;

    const float n = n_dev[cb];
    const float countv = (ncnt + EPS_F) / (n + VOCAB * EPS_F) * n;
    out[OFF_NCB + i] = __fdividef(nw, countv);
}

extern "C" void kernel_launch(void* const* d_in, const int* in_sizes, int n_in,
                              void* d_out, int out_size) {
    const float* z   = (const float*)d_in[0];
    const float* cbs = (const float*)d_in[1];
    const float* ec  = (const float*)d_in[2];
    const float* ew  = (const float*)d_in[3];
    float* out = (float*)d_out;

    vq_prep<<<512, 256>>>(cbs);
    dim3 gmain(64, N_CB);
    vq_main<<<gmain, 256>>>(z, cbs, ec, out);
    vq_final<<<512, 256>>>(ec, ew, out);
}

// round 13
// speedup vs baseline: 1.9934x; 1.0463x over previous
#include <cuda_runtime.h>
#include <cuda_fp16.h>
#include <cstdint>

// Problem constants
#define N_CB   8
#define VOCAB  1024
#define CDIM   16
#define HW     1024         // 32*32
#define DCH    128          // N_CB*CDIM
#define BHW    8192

// Output layout (float32, concatenated flat in reference order)
#define OFF_Q      0
#define OFF_IDX    1048576
#define OFF_COMMIT 1114112
#define OFF_NCB    1114113
#define OFF_NCNT   1245185
#define OFF_NW     1253377

#define DECAY_F 0.99f
#define ALPHA_F 0.01f
#define EPS_F   1e-5f

// staged fp16 split codebook + (-0.5||c||^2) table (recomputed every replay)
__device__ __half chi_g[N_CB * VOCAB * CDIM];
__device__ __half clo_g[N_CB * VOCAB * CDIM];
__device__ float  negh_g[N_CB * VOCAB];
// self-cleaning accumulators (zero at load; vq_final re-zeros each replay)
__device__ float cnt_scr[N_CB * VOCAB];
__device__ float sum_scr[N_CB * VOCAB * CDIM];
__device__ float n_dev[N_CB];
__device__ float commit_scr;

static __device__ __forceinline__ uint32_t smem_u32(const void* p) {
    uint32_t a;
    asm("{ .reg .u64 t; cvta.to.shared.u64 t, %1; cvt.u32.u64 %0, t; }" : "=r"(a) : "l"(p));
    return a;
}

// ---------------- smem layout (static, 46.6 KB) ----------------
#define SM_BHI 0                     // 256 rows x 48B (16 halves + 16B pad)
#define SM_BLO 12288
#define SM_AHI 24576                 // 128 rows x 48B
#define SM_ALO 30720
#define SM_ZF  36864                 // 128 x 16 fp32
#define SM_H   45056                 // 256 floats (-0.5||c||^2 chunk)
#define SM_IDX 46080                 // 128 ints
#define SM_TOT 46592

// ---------- kernel 0: stage fp16 hi/lo codebook + negh ----------
__global__ __launch_bounds__(256) void vq_prep(const float* __restrict__ cbs) {
    const int i = blockIdx.x * 256 + threadIdx.x;       // 0..131071
    const float v = cbs[i];
    const __half hi = __float2half_rn(v);
    const __half lo = __float2half_rn(v - __half2float(hi));
    chi_g[i] = hi;
    clo_g[i] = lo;
    if (i < N_CB * VOCAB) {
        const float4* cr = (const float4*)(cbs + (size_t)i * CDIM);
        float4 c0 = cr[0], c1 = cr[1], c2 = cr[2], c3 = cr[3];
        float s = c0.x*c0.x + c0.y*c0.y + c0.z*c0.z + c0.w*c0.w
                + c1.x*c1.x + c1.y*c1.y + c1.z*c1.z + c1.w*c1.w
                + c2.x*c2.x + c2.y*c2.y + c2.z*c2.z + c2.w*c2.w
                + c3.x*c3.x + c3.y*c3.y + c3.z*c3.z + c3.w*c3.w;
        negh_g[i] = -0.5f * s;
    }
}

// ---------- kernel 1: HMMA distance + argmin + fused epilogue ----------
// grid (64, 8): x = 128-position tile, y = codebook. 256 threads (8 warps).
// warp w owns positions tile*128 + w*16 .. +15 (MMA M-rows).
// Inner loop: 16 vocab per iteration (two n8 groups via ldmatrix.x4).
__global__ __launch_bounds__(256) void vq_main(const float* __restrict__ z,
                                               const float* __restrict__ cbs,
                                               const float* __restrict__ ema_count,
                                               float* out) {
    __shared__ __align__(16) char smem[SM_TOT];
    __shared__ float red[8], nred[8];
    const uint32_t sb = smem_u32(smem);
    const int cb = blockIdx.y, tile = blockIdx.x;
    const int tid = threadIdx.x, lane = tid & 31, w = tid >> 5;

    const int b      = tile >> 3;
    const int hwwarp = ((tile & 7) << 7) + w * 16;
    const float* zb  = z + (size_t)b * DCH * HW + (size_t)cb * CDIM * HW;

    // ---- build A tiles (fp16 hi/lo, 48B row stride) + fp32 z copy ----
    {
        const int r  = lane & 15;          // row within warp tile
        const int jh = lane >> 4;          // 0/1 selects dim parity group
        float* zf = (float*)(smem + SM_ZF);
        #pragma unroll
        for (int j2 = 0; j2 < 8; j2++) {
            const int j = j2 * 2 + jh;
            const float v = zb[j * HW + hwwarp + r];
            const __half hi = __float2half_rn(v);
            const __half lo = __float2half_rn(v - __half2float(hi));
            const int row = w * 16 + r;
            *(__half*)(smem + SM_AHI + row * 48 + j * 2) = hi;
            *(__half*)(smem + SM_ALO + row * 48 + j * 2) = lo;
            zf[row * 16 + j] = v;
        }
    }
    __syncwarp();

    // ---- A fragments (persistent): ldmatrix.x4, canonical m16n16 pattern ----
    uint32_t ah0, ah1, ah2, ah3, al0, al1, al2, al3;
    {
        const uint32_t ofs = (uint32_t)(w * 16 * 48 + (lane & 15) * 48 + ((lane >> 4) << 4));
        uint32_t a = sb + SM_AHI + ofs;
        asm volatile("ldmatrix.sync.aligned.m8n8.x4.shared.b16 {%0,%1,%2,%3}, [%4];"
                     : "=r"(ah0), "=r"(ah1), "=r"(ah2), "=r"(ah3) : "r"(a));
        a = sb + SM_ALO + ofs;
        asm volatile("ldmatrix.sync.aligned.m8n8.x4.shared.b16 {%0,%1,%2,%3}, [%4];"
                     : "=r"(al0), "=r"(al1), "=r"(al2), "=r"(al3) : "r"(a));
    }

    float bestA = -3.0e38f, bestB = -3.0e38f;
    int   vA = 0, vB = 0;
    const int colofs = (lane & 3) * 2;     // D/B column (vocab) offset within n8
    const int nrow   = lane >> 2;          // D row group

    // B ldmatrix.x4 lane addressing (mirrors validated x2 pattern):
    // lanes 0-7:  rows vl..vl+7,   k-half 0  -> frag b0 of n-group 0
    // lanes 8-15: rows vl..vl+7,   k-half 1  -> frag b1 of n-group 0
    // lanes 16-23: rows vl+8..+15, k-half 0  -> frag b0 of n-group 1
    // lanes 24-31: rows vl+8..+15, k-half 1  -> frag b1 of n-group 1
    const uint32_t brow = (uint32_t)((lane & 7) + ((lane & 16) >> 1)) * 48
                        + (uint32_t)((lane & 8) << 1);

    for (int c = 0; c < 4; c++) {
        // ---- copy B chunk (256 vocab rows) to 48B-stride smem + h chunk ----
        {
            const size_t rbase = ((size_t)cb * VOCAB + c * 256 + tid) * CDIM;
            const uint4* sh = (const uint4*)(chi_g + rbase);
            uint4 x0 = sh[0], x1 = sh[1];
            *(uint4*)(smem + SM_BHI + tid * 48)      = x0;
            *(uint4*)(smem + SM_BHI + tid * 48 + 16) = x1;
            const uint4* sl = (const uint4*)(clo_g + rbase);
            uint4 y0 = sl[0], y1 = sl[1];
            *(uint4*)(smem + SM_BLO + tid * 48)      = y0;
            *(uint4*)(smem + SM_BLO + tid * 48 + 16) = y1;
            ((float*)(smem + SM_H))[tid] = negh_g[cb * VOCAB + c * 256 + tid];
        }
        __syncthreads();

        #pragma unroll 2
        for (int it = 0; it < 16; it++) {
            const int vl = it * 16;
            const uint32_t baddr = sb + (uint32_t)(vl * 48) + brow;
            uint32_t bh0, bh1, bh2, bh3, bl0, bl1, bl2, bl3;
            asm volatile("ldmatrix.sync.aligned.m8n8.x4.shared.b16 {%0,%1,%2,%3}, [%4];"
                         : "=r"(bh0), "=r"(bh1), "=r"(bh2), "=r"(bh3) : "r"(baddr + SM_BHI));
            asm volatile("ldmatrix.sync.aligned.m8n8.x4.shared.b16 {%0,%1,%2,%3}, [%4];"
                         : "=r"(bl0), "=r"(bl1), "=r"(bl2), "=r"(bl3) : "r"(baddr + SM_BLO));
            const float2 h0 = *(const float2*)(smem + SM_H + (vl + colofs) * 4);
            const float2 h1 = *(const float2*)(smem + SM_H + (vl + 8 + colofs) * 4);

            float d0, d1, d2, d3, e0, e1, e2, e3;
            // n-group 0 (vocab vl..vl+7)
            asm volatile("mma.sync.aligned.m16n8k16.row.col.f32.f16.f16.f32 "
                "{%0,%1,%2,%3}, {%4,%5,%6,%7}, {%8,%9}, {%10,%11,%12,%13};"
                : "=f"(d0), "=f"(d1), "=f"(d2), "=f"(d3)
                : "r"(ah0), "r"(ah1), "r"(ah2), "r"(ah3), "r"(bh0), "r"(bh1),
                  "f"(h0.x), "f"(h0.y), "f"(h0.x), "f"(h0.y));
            // n-group 1 (vocab vl+8..vl+15)
            asm volatile("mma.sync.aligned.m16n8k16.row.col.f32.f16.f16.f32 "
                "{%0,%1,%2,%3}, {%4,%5,%6,%7}, {%8,%9}, {%10,%11,%12,%13};"
                : "=f"(e0), "=f"(e1), "=f"(e2), "=f"(e3)
                : "r"(ah0), "r"(ah1), "r"(ah2), "r"(ah3), "r"(bh2), "r"(bh3),
                  "f"(h1.x), "f"(h1.y), "f"(h1.x), "f"(h1.y));
            asm volatile("mma.sync.aligned.m16n8k16.row.col.f32.f16.f16.f32 "
                "{%0,%1,%2,%3}, {%4,%5,%6,%7}, {%8,%9}, {%0,%1,%2,%3};"
                : "+f"(d0), "+f"(d1), "+f"(d2), "+f"(d3)
                : "r"(al0), "r"(al1), "r"(al2), "r"(al3), "r"(bh0), "r"(bh1));
            asm volatile("mma.sync.aligned.m16n8k16.row.col.f32.f16.f16.f32 "
                "{%0,%1,%2,%3}, {%4,%5,%6,%7}, {%8,%9}, {%0,%1,%2,%3};"
                : "+f"(e0), "+f"(e1), "+f"(e2), "+f"(e3)
                : "r"(al0), "r"(al1), "r"(al2), "r"(al3), "r"(bh2), "r"(bh3));
            asm volatile("mma.sync.aligned.m16n8k16.row.col.f32.f16.f16.f32 "
                "{%0,%1,%2,%3}, {%4,%5,%6,%7}, {%8,%9}, {%0,%1,%2,%3};"
                : "+f"(d0), "+f"(d1), "+f"(d2), "+f"(d3)
                : "r"(ah0), "r"(ah1), "r"(ah2), "r"(ah3), "r"(bl0), "r"(bl1));
            asm volatile("mma.sync.aligned.m16n8k16.row.col.f32.f16.f16.f32 "
                "{%0,%1,%2,%3}, {%4,%5,%6,%7}, {%8,%9}, {%0,%1,%2,%3};"
                : "+f"(e0), "+f"(e1), "+f"(e2), "+f"(e3)
                : "r"(ah0), "r"(ah1), "r"(ah2), "r"(ah3), "r"(bl2), "r"(bl3));

            const int v0 = c * 256 + vl + colofs;
            if (d0 > bestA) { bestA = d0; vA = v0; }
            if (d1 > bestA) { bestA = d1; vA = v0 + 1; }
            if (e0 > bestA) { bestA = e0; vA = v0 + 8; }
            if (e1 > bestA) { bestA = e1; vA = v0 + 9; }
            if (d2 > bestB) { bestB = d2; vB = v0; }
            if (d3 > bestB) { bestB = d3; vB = v0 + 1; }
            if (e2 > bestB) { bestB = e2; vB = v0 + 8; }
            if (e3 > bestB) { bestB = e3; vB = v0 + 9; }
        }
        __syncthreads();
    }

    // ---- merge argmax within each quad (lanes sharing a D row) ----
    #pragma unroll
    for (int st = 1; st <= 2; st <<= 1) {
        float so = __shfl_xor_sync(0xFFFFFFFFu, bestA, st);
        int   vo = __shfl_xor_sync(0xFFFFFFFFu, vA, st);
        if (so > bestA || (so == bestA && vo < vA)) { bestA = so; vA = vo; }
        so = __shfl_xor_sync(0xFFFFFFFFu, bestB, st);
        vo = __shfl_xor_sync(0xFFFFFFFFu, vB, st);
        if (so > bestB || (so == bestB && vo < vB)) { bestB = so; vB = vo; }
    }
    if ((lane & 3) == 0) {
        int* idxs = (int*)(smem + SM_IDX);
        idxs[w * 16 + nrow]     = vA;
        idxs[w * 16 + nrow + 8] = vB;
    }
    __syncthreads();

    // ---- fused epilogue: 2 threads per position (8 dims each) ----
    const int pl  = tid >> 1;
    const int j0  = (tid & 1) * 8;
    const int bi  = ((int*)(smem + SM_IDX))[pl];
    const int hwp = ((tile & 7) << 7) + pl;
    const float* crow = cbs + ((size_t)cb * VOCAB + bi) * CDIM + j0;
    const float* zf   = (float*)(smem + SM_ZF) + pl * 16 + j0;
    float* qout = out + OFF_Q + (size_t)b * DCH * HW + (size_t)cb * CDIM * HW
                + (size_t)j0 * HW + hwp;
    float* wdst = sum_scr + ((size_t)cb * VOCAB + bi) * CDIM + j0;

    float locc = 0.0f;
    #pragma unroll
    for (int jj = 0; jj < 8; jj++) {
        const float zj = zf[jj];
        const float cj = crow[jj];
        qout[(size_t)jj * HW] = zj + (cj - zj);      // match zq_st rounding
        const float d = zj - cj;
        locc += d * d;
        atomicAdd(&wdst[jj], zj);
    }
    if ((tid & 1) == 0) {
        out[OFF_IDX + (size_t)b * (N_CB * HW) + (size_t)cb * HW + hwp] = (float)bi;
        atomicAdd(&cnt_scr[cb * VOCAB + bi], 1.0f);
    }

    // commitment: shuffle reduce -> 1 atomic per block
    #pragma unroll
    for (int st = 16; st > 0; st >>= 1)
        locc += __shfl_xor_sync(0xFFFFFFFFu, locc, st);
    if (lane == 0) red[w] = locc;
    __syncthreads();
    if (tid == 0) {
        float s = 0.0f;
        #pragma unroll
        for (int k = 0; k < 8; k++) s += red[k];
        atomicAdd(&commit_scr, s * (1.0f / (float)(BHW * N_CB * CDIM)));
    }

    // tile==0 blocks compute n[cb] = 0.99*sum(ema_count[cb]) + 0.01*BHW
    if (tile == 0) {
        float s = ema_count[cb * VOCAB + tid]       + ema_count[cb * VOCAB + tid + 256]
                + ema_count[cb * VOCAB + tid + 512] + ema_count[cb * VOCAB + tid + 768];
        #pragma unroll
        for (int st = 16; st > 0; st >>= 1)
            s += __shfl_xor_sync(0xFFFFFFFFu, s, st);
        if (lane == 0) nred[w] = s;
        __syncthreads();
        if (tid == 0) {
            float t = 0.0f;
            #pragma unroll
            for (int k = 0; k < 8; k++) t += nred[k];
            n_dev[cb] = DECAY_F * t + ALPHA_F * (float)BHW;
        }
    }
}

// ---------- kernel 2: EMA blend + normalized codebook + commit emit ----------
__global__ __launch_bounds__(256) void vq_final(const float* __restrict__ ema_count,
                                                const float* __restrict__ ema_weight,
                                                float* out) {
    const int i  = blockIdx.x * 256 + threadIdx.x;    // 0 .. 131071
    const int cb = i >> 14;
    const int v  = (i >> 4) & (VOCAB - 1);
    const int j  = i & 15;

    if (i == 0) { out[OFF_COMMIT] = commit_scr; commit_scr = 0.0f; }

    const float sums = sum_scr[i];
    sum_scr[i] = 0.0f;                                // self-clean
    const float nw = DECAY_F * ema_weight[i] + ALPHA_F * sums;
    out[OFF_NW + i] = nw;

    const float craw = cnt_scr[cb * VOCAB + v];
    __syncwarp();
    if (j == 0) cnt_scr[cb * VOCAB + v] = 0.0f;       // self-clean

    const float ncnt = DECAY_F * ema_count[cb * VOCAB + v] + ALPHA_F * craw;
    if (j == 0) out[OFF_NCNT + cb * VOCAB + v] = ncnt;

    const float n = n_dev[cb];
    const float countv = (ncnt + EPS_F) / (n + VOCAB * EPS_F) * n;
    out[OFF_NCB + i] = __fdividef(nw, countv);
}

extern "C" void kernel_launch(void* const* d_in, const int* in_sizes, int n_in,
                              void* d_out, int out_size) {
    const float* z   = (const float*)d_in[0];
    const float* cbs = (const float*)d_in[1];
    const float* ec  = (const float*)d_in[2];
    const float* ew  = (const float*)d_in[3];
    float* out = (float*)d_out;

    vq_prep<<<512, 256>>>(cbs);
    dim3 gmain(64, N_CB);
    vq_main<<<gmain, 256>>>(z, cbs, ec, out);
    vq_final<<<512, 256>>>(ec, ew, out);
}